// round 7
// baseline (speedup 1.0000x reference)
#include <cuda_runtime.h>
#include <cuda_bf16.h>
#include <mma.h>
#include <math.h>

using namespace nvcuda;

#define MROWS 200704   // B*H*W = 64*56*56
#define CDIM  128
#define BATCH 64
#define HH    56
#define WWD   56
#define LHW   3136

// ---------------- scratch (static device memory; no allocs) ----------------
__device__ float g_bufA[MROWS*CDIM];       // ctx ping-pong
__device__ float g_bufB[MROWS*CDIM];
__device__ float g_q[MROWS*CDIM];          // q (fp32)
__device__ float g_ctxall[MROWS*CDIM];     // gated ctx accumulator
__device__ float g_x1[MROWS*CDIM];         // shortcut + x_out
__device__ float g_gates[MROWS*4];
__device__ float g_msum[BATCH*CDIM];
__device__ float g_mg[BATCH*CDIM];         // gelu(mean ctx)
__device__ __nv_bfloat16 g_y[MROWS*CDIM];  // LN1 out (bf16)
// bf16 weights (g_wf padded N 260 -> 320)
__device__ __nv_bfloat16 g_wf[128*320];
__device__ __nv_bfloat16 g_wh[128*128];
__device__ __nv_bfloat16 g_wp[128*128];
__device__ __nv_bfloat16 g_w1[128*512];
__device__ __nv_bfloat16 g_w2[512*128];

__device__ __forceinline__ float gelu1(float v){
    return 0.5f * v * (1.0f + erff(v * 0.70710678118654752f));
}

// ---------------- weight fp32 -> bf16 (with N padding) ----------------
__global__ void wconv_kernel(const float* __restrict__ src, int id, int K, int N, int NLD){
    int i = blockIdx.x*256 + threadIdx.x;
    if (i >= K*NLD) return;
    int r = i / NLD, cl = i - r*NLD;
    float v = (cl < N) ? src[r*N + cl] : 0.0f;
    __nv_bfloat16 bv = __float2bfloat16(v);
    if      (id==0) g_wf[i]=bv;
    else if (id==1) g_wh[i]=bv;
    else if (id==2) g_wp[i]=bv;
    else if (id==3) g_w1[i]=bv;
    else            g_w2[i]=bv;
}

// ---------------- LayerNorm (one warp per row of 128) ----------------
__global__ void __launch_bounds__(256) ln_kernel(const float* __restrict__ xin,
                                                 const float* __restrict__ gw,
                                                 const float* __restrict__ bw)
{
    int row  = blockIdx.x*8 + (threadIdx.x>>5);
    int lane = threadIdx.x & 31;
    float4 v = *(const float4*)(xin + row*CDIM + lane*4);
    float s  = v.x+v.y+v.z+v.w;
    float s2 = v.x*v.x + v.y*v.y + v.z*v.z + v.w*v.w;
    #pragma unroll
    for (int o=16;o;o>>=1){
        s  += __shfl_xor_sync(0xffffffffu, s,  o);
        s2 += __shfl_xor_sync(0xffffffffu, s2, o);
    }
    float mu  = s  * (1.0f/128.0f);
    float var = s2 * (1.0f/128.0f) - mu*mu;
    float rs  = rsqrtf(var + 1e-5f);
    float4 gg = *(const float4*)(gw + lane*4);
    float4 bb = *(const float4*)(bw + lane*4);
    float r0 = (v.x-mu)*rs*gg.x + bb.x;
    float r1 = (v.y-mu)*rs*gg.y + bb.y;
    float r2 = (v.z-mu)*rs*gg.z + bb.z;
    float r3 = (v.w-mu)*rs*gg.w + bb.w;
    __nv_bfloat162* o2 = (__nv_bfloat162*)(g_y + row*CDIM + lane*4);
    o2[0] = __floats2bfloat162_rn(r0, r1);
    o2[1] = __floats2bfloat162_rn(r2, r3);
}

// ================= GEMM 1: t = y @ f_w + f_b  -> q / ctx / gates ============
// BM=128, BN=64, K=128. smem: A[128][136] bf16 | B[128][72] bf16; stage f32 reuses A.
#define LDA 136
__global__ void __launch_bounds__(256,1) g1_kernel(const float* __restrict__ f_b)
{
    extern __shared__ char dsm[];
    __nv_bfloat16* smA = (__nv_bfloat16*)dsm;              // 128*136*2 = 34816
    __nv_bfloat16* smB = (__nv_bfloat16*)(dsm + 34816);    // 128*72*2  = 18432
    const int LDB = 72;
    const int tid  = threadIdx.x;
    const int warp = tid >> 5;
    const int wm   = warp >> 1, wn = warp & 1;
    const int n0   = blockIdx.x * 64;
    const int row0 = blockIdx.y * 128;

    // stage A (g_y) 128x128 bf16
    for (int i = tid; i < 128*16; i += 256){
        int r = i >> 4, c = (i & 15) * 8;
        *(uint4*)(smA + r*LDA + c) = *(const uint4*)(g_y + (size_t)(row0+r)*128 + c);
    }
    // stage B (g_wf, stride 320) 128x64
    for (int i = tid; i < 128*8; i += 256){
        int r = i >> 3, c = (i & 7) * 8;
        *(uint4*)(smB + r*LDB + c) = *(const uint4*)(g_wf + (size_t)r*320 + n0 + c);
    }
    __syncthreads();

    wmma::fragment<wmma::accumulator,16,16,16,float> acc[2][2];
    #pragma unroll
    for (int i=0;i<2;i++) for (int j=0;j<2;j++) wmma::fill_fragment(acc[i][j], 0.0f);

    #pragma unroll
    for (int k=0;k<128;k+=16){
        wmma::fragment<wmma::matrix_a,16,16,16,__nv_bfloat16,wmma::row_major> a[2];
        wmma::fragment<wmma::matrix_b,16,16,16,__nv_bfloat16,wmma::row_major> b[2];
        wmma::load_matrix_sync(a[0], smA + (wm*32   )*LDA + k, LDA);
        wmma::load_matrix_sync(a[1], smA + (wm*32+16)*LDA + k, LDA);
        wmma::load_matrix_sync(b[0], smB + k*LDB + wn*32,      LDB);
        wmma::load_matrix_sync(b[1], smB + k*LDB + wn*32 + 16, LDB);
        #pragma unroll
        for (int i=0;i<2;i++) for (int j=0;j<2;j++) wmma::mma_sync(acc[i][j], a[i], b[j], acc[i][j]);
    }
    __syncthreads();
    float* st = (float*)dsm;   // 128x64 f32 (32KB) over A region
    #pragma unroll
    for (int i=0;i<2;i++) for (int j=0;j<2;j++)
        wmma::store_matrix_sync(st + (wm*32+i*16)*64 + wn*32 + j*16, acc[i][j], 64, wmma::mem_row_major);
    __syncthreads();

    for (int i = tid; i < 128*64; i += 256){
        int r = i >> 6, c = i & 63;
        int grow = row0 + r, gcol = n0 + c;
        if (gcol >= 260) continue;
        float v = st[i] + f_b[gcol];
        if (gcol < 128)      g_q[grow*128 + gcol] = v;
        else if (gcol < 256) g_bufA[grow*128 + gcol - 128] = v;
        else                 g_gates[grow*4 + gcol - 256] = v;
    }
}

// ===== fused: cab -> (@h_w + h_b) -> *q -> (@proj_w + proj_b) -> +x -> x1 ===
__global__ void __launch_bounds__(256,1) g2_kernel(const float* __restrict__ h_b,
                                                   const float* __restrict__ proj_b,
                                                   const float* __restrict__ xin)
{
    extern __shared__ char dsm[];
    __nv_bfloat16* smA = (__nv_bfloat16*)dsm;              // 128*136*2 = 34816
    __nv_bfloat16* smB = (__nv_bfloat16*)(dsm + 34816);    // 128*136*2 = 34816
    float*         st  = (float*)(dsm + 69632);            // 128*128*4 = 65536
    const int LDB = 136;
    const int tid  = threadIdx.x;
    const int warp = tid >> 5;
    const int wm   = warp >> 1, wn = warp & 1;
    const int row0 = blockIdx.x * 128;

    // stage A = bf16(ctx_all + gelu_mean * gate3)
    for (int i = tid; i < 128*32; i += 256){
        int r = i >> 5, c4 = (i & 31) * 4;
        int grow = row0 + r;
        int b = grow / LHW;
        float gate = g_gates[grow*4 + 3];
        float4 ca = *(const float4*)(g_ctxall + (size_t)grow*128 + c4);
        float4 mg = *(const float4*)(g_mg + b*128 + c4);
        __nv_bfloat162 p0 = __floats2bfloat162_rn(ca.x + mg.x*gate, ca.y + mg.y*gate);
        __nv_bfloat162 p1 = __floats2bfloat162_rn(ca.z + mg.z*gate, ca.w + mg.w*gate);
        *(__nv_bfloat162*)(smA + r*LDA + c4)     = p0;
        *(__nv_bfloat162*)(smA + r*LDA + c4 + 2) = p1;
    }
    // stage B = h_w
    for (int i = tid; i < 128*16; i += 256){
        int r = i >> 4, c = (i & 15) * 8;
        *(uint4*)(smB + r*LDB + c) = *(const uint4*)(g_wh + (size_t)r*128 + c);
    }
    __syncthreads();

    wmma::fragment<wmma::accumulator,16,16,16,float> acc[2][4];
    #pragma unroll
    for (int i=0;i<2;i++) for (int j=0;j<4;j++) wmma::fill_fragment(acc[i][j], 0.0f);
    #pragma unroll
    for (int k=0;k<128;k+=16){
        wmma::fragment<wmma::matrix_a,16,16,16,__nv_bfloat16,wmma::row_major> a[2];
        wmma::fragment<wmma::matrix_b,16,16,16,__nv_bfloat16,wmma::row_major> b[4];
        wmma::load_matrix_sync(a[0], smA + (wm*32   )*LDA + k, LDA);
        wmma::load_matrix_sync(a[1], smA + (wm*32+16)*LDA + k, LDA);
        #pragma unroll
        for (int j=0;j<4;j++) wmma::load_matrix_sync(b[j], smB + k*LDB + wn*64 + j*16, LDB);
        #pragma unroll
        for (int i=0;i<2;i++) for (int j=0;j<4;j++) wmma::mma_sync(acc[i][j], a[i], b[j], acc[i][j]);
    }
    __syncthreads();
    #pragma unroll
    for (int i=0;i<2;i++) for (int j=0;j<4;j++)
        wmma::store_matrix_sync(st + (wm*32+i*16)*128 + wn*64 + j*16, acc[i][j], 128, wmma::mem_row_major);
    __syncthreads();

    // xq = (mod + h_b) * q  -> smA (bf16), and restage smB = proj_w
    for (int i = tid; i < 128*128; i += 256){
        int r = i >> 7, c = i & 127;
        float v = (st[i] + h_b[c]) * g_q[(size_t)(row0+r)*128 + c];
        smA[r*LDA + c] = __float2bfloat16(v);
    }
    for (int i = tid; i < 128*16; i += 256){
        int r = i >> 4, c = (i & 15) * 8;
        *(uint4*)(smB + r*LDB + c) = *(const uint4*)(g_wp + (size_t)r*128 + c);
    }
    __syncthreads();

    #pragma unroll
    for (int i=0;i<2;i++) for (int j=0;j<4;j++) wmma::fill_fragment(acc[i][j], 0.0f);
    #pragma unroll
    for (int k=0;k<128;k+=16){
        wmma::fragment<wmma::matrix_a,16,16,16,__nv_bfloat16,wmma::row_major> a[2];
        wmma::fragment<wmma::matrix_b,16,16,16,__nv_bfloat16,wmma::row_major> b[4];
        wmma::load_matrix_sync(a[0], smA + (wm*32   )*LDA + k, LDA);
        wmma::load_matrix_sync(a[1], smA + (wm*32+16)*LDA + k, LDA);
        #pragma unroll
        for (int j=0;j<4;j++) wmma::load_matrix_sync(b[j], smB + k*LDB + wn*64 + j*16, LDB);
        #pragma unroll
        for (int i=0;i<2;i++) for (int j=0;j<4;j++) wmma::mma_sync(acc[i][j], a[i], b[j], acc[i][j]);
    }
    __syncthreads();
    #pragma unroll
    for (int i=0;i<2;i++) for (int j=0;j<4;j++)
        wmma::store_matrix_sync(st + (wm*32+i*16)*128 + wn*64 + j*16, acc[i][j], 128, wmma::mem_row_major);
    __syncthreads();

    for (int i = tid; i < 128*128; i += 256){
        int r = i >> 7, c = i & 127;
        size_t g = (size_t)(row0+r)*128 + c;
        g_x1[g] = st[i] + proj_b[c] + xin[g];
    }
}

// ===== fused MLP: LN2 -> gelu(m@W1+b1) -> @W2 + b2 + x1 -> out =============
__global__ void __launch_bounds__(256,1) g3_kernel(const float* __restrict__ ln2_g,
                                                   const float* __restrict__ ln2_b,
                                                   const float* __restrict__ fc1_b,
                                                   const float* __restrict__ fc2_b,
                                                   float* __restrict__ fout)
{
    extern __shared__ char dsm[];
    __nv_bfloat16* smA  = (__nv_bfloat16*)dsm;             // 128*136*2 = 34816
    __nv_bfloat16* smW1 = (__nv_bfloat16*)(dsm + 34816);   // 128*72*2  = 18432
    __nv_bfloat16* smH  = (__nv_bfloat16*)(dsm + 53248);   // 128*72*2  = 18432
    __nv_bfloat16* smW2 = (__nv_bfloat16*)(dsm + 71680);   // 64*136*2  = 17408
    float*         st   = (float*)(dsm + 89088);           // 128*64*4  = 32768
    const int LD72 = 72, LD136 = 136;
    const int tid  = threadIdx.x;
    const int warp = tid >> 5, lane = tid & 31;
    const int wm   = warp >> 1, wn = warp & 1;
    const int row0 = blockIdx.x * 128;

    // LN2 staging: each warp handles 16 rows
    for (int rr = 0; rr < 16; rr++){
        int r = warp*16 + rr;
        size_t g = (size_t)(row0 + r)*128 + lane*4;
        float4 v = *(const float4*)(g_x1 + g);
        float s  = v.x+v.y+v.z+v.w;
        float s2 = v.x*v.x+v.y*v.y+v.z*v.z+v.w*v.w;
        #pragma unroll
        for (int o=16;o;o>>=1){
            s  += __shfl_xor_sync(0xffffffffu, s,  o);
            s2 += __shfl_xor_sync(0xffffffffu, s2, o);
        }
        float mu  = s * (1.0f/128.0f);
        float var = s2 * (1.0f/128.0f) - mu*mu;
        float rs  = rsqrtf(var + 1e-5f);
        float4 gg = *(const float4*)(ln2_g + lane*4);
        float4 bb = *(const float4*)(ln2_b + lane*4);
        __nv_bfloat162 p0 = __floats2bfloat162_rn((v.x-mu)*rs*gg.x + bb.x, (v.y-mu)*rs*gg.y + bb.y);
        __nv_bfloat162 p1 = __floats2bfloat162_rn((v.z-mu)*rs*gg.z + bb.z, (v.w-mu)*rs*gg.w + bb.w);
        *(__nv_bfloat162*)(smA + r*LDA + lane*4)     = p0;
        *(__nv_bfloat162*)(smA + r*LDA + lane*4 + 2) = p1;
    }

    wmma::fragment<wmma::accumulator,16,16,16,float> acc2[2][4];
    #pragma unroll
    for (int i=0;i<2;i++) for (int j=0;j<4;j++) wmma::fill_fragment(acc2[i][j], 0.0f);

    for (int nc = 0; nc < 8; nc++){
        // stage W1 chunk [128 x 64] (stride 512) and W2 chunk [64 x 128] (stride 128)
        for (int i = tid; i < 128*8; i += 256){
            int r = i >> 3, c = (i & 7) * 8;
            *(uint4*)(smW1 + r*LD72 + c) = *(const uint4*)(g_w1 + (size_t)r*512 + nc*64 + c);
        }
        for (int i = tid; i < 64*16; i += 256){
            int r = i >> 4, c = (i & 15) * 8;
            *(uint4*)(smW2 + r*LD136 + c) = *(const uint4*)(g_w2 + (size_t)(nc*64 + r)*128 + c);
        }
        __syncthreads();

        // h_chunk = m @ W1c  (128x64x128)
        wmma::fragment<wmma::accumulator,16,16,16,float> acc1[2][2];
        #pragma unroll
        for (int i=0;i<2;i++) for (int j=0;j<2;j++) wmma::fill_fragment(acc1[i][j], 0.0f);
        #pragma unroll
        for (int k=0;k<128;k+=16){
            wmma::fragment<wmma::matrix_a,16,16,16,__nv_bfloat16,wmma::row_major> a[2];
            wmma::fragment<wmma::matrix_b,16,16,16,__nv_bfloat16,wmma::row_major> b[2];
            wmma::load_matrix_sync(a[0], smA + (wm*32   )*LDA + k, LDA);
            wmma::load_matrix_sync(a[1], smA + (wm*32+16)*LDA + k, LDA);
            wmma::load_matrix_sync(b[0], smW1 + k*LD72 + wn*32,      LD72);
            wmma::load_matrix_sync(b[1], smW1 + k*LD72 + wn*32 + 16, LD72);
            #pragma unroll
            for (int i=0;i<2;i++) for (int j=0;j<2;j++) wmma::mma_sync(acc1[i][j], a[i], b[j], acc1[i][j]);
        }
        __syncthreads();
        #pragma unroll
        for (int i=0;i<2;i++) for (int j=0;j<2;j++)
            wmma::store_matrix_sync(st + (wm*32+i*16)*64 + wn*32 + j*16, acc1[i][j], 64, wmma::mem_row_major);
        __syncthreads();

        // gelu -> smH (bf16)
        for (int i = tid; i < 128*64; i += 256){
            int r = i >> 6, c = i & 63;
            float v = gelu1(st[i] + fc1_b[nc*64 + c]);
            smH[r*LD72 + c] = __float2bfloat16(v);
        }
        __syncthreads();

        // acc2 += h_chunk @ W2c  (128x128x64)
        #pragma unroll
        for (int k=0;k<64;k+=16){
            wmma::fragment<wmma::matrix_a,16,16,16,__nv_bfloat16,wmma::row_major> a[2];
            wmma::fragment<wmma::matrix_b,16,16,16,__nv_bfloat16,wmma::row_major> b[4];
            wmma::load_matrix_sync(a[0], smH + (wm*32   )*LD72 + k, LD72);
            wmma::load_matrix_sync(a[1], smH + (wm*32+16)*LD72 + k, LD72);
            #pragma unroll
            for (int j=0;j<4;j++) wmma::load_matrix_sync(b[j], smW2 + k*LD136 + wn*64 + j*16, LD136);
            #pragma unroll
            for (int i=0;i<2;i++) for (int j=0;j<4;j++) wmma::mma_sync(acc2[i][j], a[i], b[j], acc2[i][j]);
        }
        __syncthreads();
    }

    // final epilogue: out = acc2 + fc2_b + x1
    float* stO = (float*)dsm;  // 128x128 f32 (64KB) over smA/smW1/smH
    #pragma unroll
    for (int i=0;i<2;i++) for (int j=0;j<4;j++)
        wmma::store_matrix_sync(stO + (wm*32+i*16)*128 + wn*64 + j*16, acc2[i][j], 128, wmma::mem_row_major);
    __syncthreads();
    for (int i = tid; i < 128*128; i += 256){
        int r = i >> 7, c = i & 127;
        size_t g = (size_t)(row0+r)*128 + c;
        fout[g] = stO[i] + fc2_b[c] + g_x1[g];
    }
}

// ---------------- depthwise conv + gelu + gated accumulate ----------------
template<int KS, int LEVEL>
__global__ void __launch_bounds__(256) dwconv_kernel(const float* __restrict__ kern)
{
    __shared__ float sk[KS*KS*CDIM];
    const float* in;
    float* out;
    if      constexpr (LEVEL==0){ in = g_bufA; out = g_bufB; }
    else if constexpr (LEVEL==1){ in = g_bufB; out = g_bufA; }
    else                        { in = g_bufA; out = g_bufB; }

    int tid = threadIdx.y*32 + threadIdx.x;
    for (int i = tid; i < KS*KS*CDIM; i += 256) sk[i] = kern[i];
    __syncthreads();

    int row = blockIdx.x*8 + threadIdx.y;
    int c0  = threadIdx.x * 4;
    int b   = row / LHW;
    int hw  = row - b*LHW;
    int h   = hw / WWD;
    int w   = hw - h*WWD;
    constexpr int P = KS/2;
    float4 acc = make_float4(0.f,0.f,0.f,0.f);
    const float* base = in + (size_t)b*LHW*CDIM + c0;
    #pragma unroll
    for (int kh=0; kh<KS; kh++){
        int hh = h + kh - P;
        if ((unsigned)hh >= HH) continue;
        #pragma unroll
        for (int kw=0; kw<KS; kw++){
            int ww2 = w + kw - P;
            if ((unsigned)ww2 >= WWD) continue;
            float4 vi = *(const float4*)(base + (size_t)(hh*WWD + ww2)*CDIM);
            const float* kp = &sk[(kh*KS+kw)*CDIM + c0];
            acc.x += vi.x*kp[0];
            acc.y += vi.y*kp[1];
            acc.z += vi.z*kp[2];
            acc.w += vi.w*kp[3];
        }
    }
    acc.x = gelu1(acc.x); acc.y = gelu1(acc.y);
    acc.z = gelu1(acc.z); acc.w = gelu1(acc.w);
    *(float4*)(out + (size_t)row*CDIM + c0) = acc;
    float gate = g_gates[row*4 + LEVEL];
    float4* ca = (float4*)(g_ctxall + (size_t)row*CDIM + c0);
    if constexpr (LEVEL==0) {
        *ca = make_float4(acc.x*gate, acc.y*gate, acc.z*gate, acc.w*gate);
    } else {
        float4 o = *ca;
        *ca = make_float4(o.x+acc.x*gate, o.y+acc.y*gate, o.z+acc.z*gate, o.w+acc.w*gate);
    }
}

// ---------------- global-context mean over H,W ----------------
__global__ void mean_zero_kernel(){
    int i = blockIdx.x*256 + threadIdx.x;
    if (i < BATCH*CDIM) g_msum[i] = 0.f;
}
__global__ void mean_partial_kernel(){
    int b = blockIdx.x, chunk = blockIdx.y, c = threadIdx.x;  // 128 threads
    const float* p = g_bufB + ((size_t)b*LHW + chunk*196)*CDIM + c;
    float s = 0.f;
    #pragma unroll 4
    for (int i=0;i<196;i++) s += p[i*CDIM];
    atomicAdd(&g_msum[b*CDIM + c], s);
}
__global__ void mean_final_kernel(){
    int i = blockIdx.x*256 + threadIdx.x;
    if (i < BATCH*CDIM) g_mg[i] = gelu1(g_msum[i] * (1.0f/3136.0f));
}

// ---------------- launch ----------------
extern "C" void kernel_launch(void* const* d_in, const int* in_sizes, int n_in,
                              void* d_out, int out_size)
{
    const float* x      = (const float*)d_in[0];
    const float* f_w    = (const float*)d_in[1];
    const float* f_b    = (const float*)d_in[2];
    const float* k0     = (const float*)d_in[3];
    const float* k1     = (const float*)d_in[4];
    const float* k2     = (const float*)d_in[5];
    const float* h_w    = (const float*)d_in[6];
    const float* h_b    = (const float*)d_in[7];
    const float* proj_w = (const float*)d_in[8];
    const float* proj_b = (const float*)d_in[9];
    const float* ln1_g  = (const float*)d_in[10];
    const float* ln1_b  = (const float*)d_in[11];
    const float* ln2_g  = (const float*)d_in[12];
    const float* ln2_b  = (const float*)d_in[13];
    const float* fc1_w  = (const float*)d_in[14];
    const float* fc1_b  = (const float*)d_in[15];
    const float* fc2_w  = (const float*)d_in[16];
    const float* fc2_b  = (const float*)d_in[17];
    float* out = (float*)d_out;

    // allow >48KB dynamic smem (host-side attr set; not a graphed op)
    cudaFuncSetAttribute(g1_kernel, cudaFuncAttributeMaxDynamicSharedMemorySize, 53248);
    cudaFuncSetAttribute(g2_kernel, cudaFuncAttributeMaxDynamicSharedMemorySize, 135168);
    cudaFuncSetAttribute(g3_kernel, cudaFuncAttributeMaxDynamicSharedMemorySize, 121856);

    // weights -> bf16
    wconv_kernel<<<(128*320+255)/256,256>>>(f_w,    0, 128, 260, 320);
    wconv_kernel<<<(128*128+255)/256,256>>>(h_w,    1, 128, 128, 128);
    wconv_kernel<<<(128*128+255)/256,256>>>(proj_w, 2, 128, 128, 128);
    wconv_kernel<<<(128*512+255)/256,256>>>(fc1_w,  3, 128, 512, 512);
    wconv_kernel<<<(512*128+255)/256,256>>>(fc2_w,  4, 512, 128, 128);

    const int rowBlocks = MROWS/8;
    dim3 cblk(32,8);

    // LN1 -> y (bf16)
    ln_kernel<<<rowBlocks,256>>>(x, ln1_g, ln1_b);

    // t = y@f_w + f_b -> q / ctx(g_bufA) / gates
    dim3 gb1(5, MROWS/128);
    g1_kernel<<<gb1, 256, 53248>>>(f_b);

    // focal levels: conv+gelu+gated accumulate
    dwconv_kernel<3,0><<<rowBlocks,cblk>>>(k0);  // bufA -> bufB
    dwconv_kernel<5,1><<<rowBlocks,cblk>>>(k1);  // bufB -> bufA
    dwconv_kernel<7,2><<<rowBlocks,cblk>>>(k2);  // bufA -> bufB

    // global context: gelu(mean over H,W of last ctx)
    mean_zero_kernel<<<32,256>>>();
    dim3 gmp(64,16);
    mean_partial_kernel<<<gmp,128>>>();
    mean_final_kernel<<<32,256>>>();

    // fused cab -> modulator -> *q -> proj -> +x  => x1
    g2_kernel<<<MROWS/128, 256, 135168>>>(h_b, proj_b, x);

    // fused LN2 -> MLP -> +x1 => out
    g3_kernel<<<MROWS/128, 256, 121856>>>(ln2_g, ln2_b, fc1_b, fc2_b, out);
}

// round 10
// speedup vs baseline: 1.0010x; 1.0010x over previous
#include <cuda_runtime.h>
#include <cuda_bf16.h>
#include <mma.h>
#include <math.h>

using namespace nvcuda;

#define MROWS 200704   // B*H*W = 64*56*56
#define CDIM  128
#define BATCH 64
#define HH    56
#define WWD   56
#define LHW   3136

// ---------------- scratch (static device memory; no allocs) ----------------
__device__ float g_bufA[MROWS*CDIM];       // ctx ping-pong
__device__ float g_bufB[MROWS*CDIM];
__device__ float g_q[MROWS*CDIM];          // q (fp32)
__device__ float g_ctxall[MROWS*CDIM];     // gated ctx accumulator
__device__ float g_x1[MROWS*CDIM];         // shortcut + x_out
__device__ float g_gates[MROWS*4];
__device__ float g_msum[BATCH*CDIM];
__device__ float g_mg[BATCH*CDIM];         // gelu(mean ctx)
__device__ __nv_bfloat16 g_y[MROWS*CDIM];  // LN1 out (bf16)
// bf16 weights (g_wf padded N 260 -> 320)
__device__ __nv_bfloat16 g_wf[128*320];
__device__ __nv_bfloat16 g_wh[128*128];
__device__ __nv_bfloat16 g_wp[128*128];
__device__ __nv_bfloat16 g_w1[128*512];
__device__ __nv_bfloat16 g_w2[512*128];

__device__ __forceinline__ float gelu1(float v){
    return 0.5f * v * (1.0f + erff(v * 0.70710678118654752f));
}

// ---------------- weight fp32 -> bf16 (with N padding) ----------------
__global__ void wconv_kernel(const float* __restrict__ src, int id, int K, int N, int NLD){
    int i = blockIdx.x*256 + threadIdx.x;
    if (i >= K*NLD) return;
    int r = i / NLD, cl = i - r*NLD;
    float v = (cl < N) ? src[r*N + cl] : 0.0f;
    __nv_bfloat16 bv = __float2bfloat16(v);
    if      (id==0) g_wf[i]=bv;
    else if (id==1) g_wh[i]=bv;
    else if (id==2) g_wp[i]=bv;
    else if (id==3) g_w1[i]=bv;
    else            g_w2[i]=bv;
}

// ---------------- LayerNorm (one warp per row of 128) ----------------
__global__ void __launch_bounds__(256) ln_kernel(const float* __restrict__ xin,
                                                 const float* __restrict__ gw,
                                                 const float* __restrict__ bw)
{
    int row  = blockIdx.x*8 + (threadIdx.x>>5);
    int lane = threadIdx.x & 31;
    float4 v = *(const float4*)(xin + row*CDIM + lane*4);
    float s  = v.x+v.y+v.z+v.w;
    float s2 = v.x*v.x + v.y*v.y + v.z*v.z + v.w*v.w;
    #pragma unroll
    for (int o=16;o;o>>=1){
        s  += __shfl_xor_sync(0xffffffffu, s,  o);
        s2 += __shfl_xor_sync(0xffffffffu, s2, o);
    }
    float mu  = s  * (1.0f/128.0f);
    float var = s2 * (1.0f/128.0f) - mu*mu;
    float rs  = rsqrtf(var + 1e-5f);
    float4 gg = *(const float4*)(gw + lane*4);
    float4 bb = *(const float4*)(bw + lane*4);
    float r0 = (v.x-mu)*rs*gg.x + bb.x;
    float r1 = (v.y-mu)*rs*gg.y + bb.y;
    float r2 = (v.z-mu)*rs*gg.z + bb.z;
    float r3 = (v.w-mu)*rs*gg.w + bb.w;
    __nv_bfloat162* o2 = (__nv_bfloat162*)(g_y + row*CDIM + lane*4);
    o2[0] = __floats2bfloat162_rn(r0, r1);
    o2[1] = __floats2bfloat162_rn(r2, r3);
}

// ================= GEMM 1: t = y @ f_w + f_b  -> q / ctx / gates ============
// BM=128, BN=64, K=128. smem: A[128][136] bf16 | B[128][72] bf16; stage f32 reuses A.
#define LDA 136
__global__ void __launch_bounds__(256,1) g1_kernel(const float* __restrict__ f_b)
{
    extern __shared__ char dsm[];
    __nv_bfloat16* smA = (__nv_bfloat16*)dsm;              // 128*136*2 = 34816
    __nv_bfloat16* smB = (__nv_bfloat16*)(dsm + 34816);    // 128*72*2  = 18432
    const int LDB = 72;
    const int tid  = threadIdx.x;
    const int warp = tid >> 5;
    const int wm   = warp >> 1, wn = warp & 1;
    const int n0   = blockIdx.x * 64;
    const int row0 = blockIdx.y * 128;

    // stage A (g_y) 128x128 bf16
    for (int i = tid; i < 128*16; i += 256){
        int r = i >> 4, c = (i & 15) * 8;
        *(uint4*)(smA + r*LDA + c) = *(const uint4*)(g_y + (size_t)(row0+r)*128 + c);
    }
    // stage B (g_wf, stride 320) 128x64
    for (int i = tid; i < 128*8; i += 256){
        int r = i >> 3, c = (i & 7) * 8;
        *(uint4*)(smB + r*LDB + c) = *(const uint4*)(g_wf + (size_t)r*320 + n0 + c);
    }
    __syncthreads();

    wmma::fragment<wmma::accumulator,16,16,16,float> acc[2][2];
    #pragma unroll
    for (int i=0;i<2;i++) for (int j=0;j<2;j++) wmma::fill_fragment(acc[i][j], 0.0f);

    #pragma unroll
    for (int k=0;k<128;k+=16){
        wmma::fragment<wmma::matrix_a,16,16,16,__nv_bfloat16,wmma::row_major> a[2];
        wmma::fragment<wmma::matrix_b,16,16,16,__nv_bfloat16,wmma::row_major> b[2];
        wmma::load_matrix_sync(a[0], smA + (wm*32   )*LDA + k, LDA);
        wmma::load_matrix_sync(a[1], smA + (wm*32+16)*LDA + k, LDA);
        wmma::load_matrix_sync(b[0], smB + k*LDB + wn*32,      LDB);
        wmma::load_matrix_sync(b[1], smB + k*LDB + wn*32 + 16, LDB);
        #pragma unroll
        for (int i=0;i<2;i++) for (int j=0;j<2;j++) wmma::mma_sync(acc[i][j], a[i], b[j], acc[i][j]);
    }
    __syncthreads();
    float* st = (float*)dsm;   // 128x64 f32 (32KB) over A region
    #pragma unroll
    for (int i=0;i<2;i++) for (int j=0;j<2;j++)
        wmma::store_matrix_sync(st + (wm*32+i*16)*64 + wn*32 + j*16, acc[i][j], 64, wmma::mem_row_major);
    __syncthreads();

    for (int i = tid; i < 128*64; i += 256){
        int r = i >> 6, c = i & 63;
        int grow = row0 + r, gcol = n0 + c;
        if (gcol >= 260) continue;
        float v = st[i] + f_b[gcol];
        if (gcol < 128)      g_q[grow*128 + gcol] = v;
        else if (gcol < 256) g_bufA[grow*128 + gcol - 128] = v;
        else                 g_gates[grow*4 + gcol - 256] = v;
    }
}

// ===== fused: cab -> (@h_w + h_b) -> *q -> (@proj_w + proj_b) -> +x -> x1 ===
__global__ void __launch_bounds__(256,1) g2_kernel(const float* __restrict__ h_b,
                                                   const float* __restrict__ proj_b,
                                                   const float* __restrict__ xin)
{
    extern __shared__ char dsm[];
    __nv_bfloat16* smA = (__nv_bfloat16*)dsm;              // 128*136*2 = 34816
    __nv_bfloat16* smB = (__nv_bfloat16*)(dsm + 34816);    // 128*136*2 = 34816
    float*         st  = (float*)(dsm + 69632);            // 128*128*4 = 65536
    const int LDB = 136;
    const int tid  = threadIdx.x;
    const int warp = tid >> 5;
    const int wm   = warp >> 1, wn = warp & 1;
    const int row0 = blockIdx.x * 128;

    // stage A = bf16(ctx_all + gelu_mean * gate3)
    for (int i = tid; i < 128*32; i += 256){
        int r = i >> 5, c4 = (i & 31) * 4;
        int grow = row0 + r;
        int b = grow / LHW;
        float gate = g_gates[grow*4 + 3];
        float4 ca = *(const float4*)(g_ctxall + (size_t)grow*128 + c4);
        float4 mg = *(const float4*)(g_mg + b*128 + c4);
        __nv_bfloat162 p0 = __floats2bfloat162_rn(ca.x + mg.x*gate, ca.y + mg.y*gate);
        __nv_bfloat162 p1 = __floats2bfloat162_rn(ca.z + mg.z*gate, ca.w + mg.w*gate);
        *(__nv_bfloat162*)(smA + r*LDA + c4)     = p0;
        *(__nv_bfloat162*)(smA + r*LDA + c4 + 2) = p1;
    }
    // stage B = h_w
    for (int i = tid; i < 128*16; i += 256){
        int r = i >> 4, c = (i & 15) * 8;
        *(uint4*)(smB + r*LDB + c) = *(const uint4*)(g_wh + (size_t)r*128 + c);
    }
    __syncthreads();

    wmma::fragment<wmma::accumulator,16,16,16,float> acc[2][4];
    #pragma unroll
    for (int i=0;i<2;i++) for (int j=0;j<4;j++) wmma::fill_fragment(acc[i][j], 0.0f);
    #pragma unroll
    for (int k=0;k<128;k+=16){
        wmma::fragment<wmma::matrix_a,16,16,16,__nv_bfloat16,wmma::row_major> a[2];
        wmma::fragment<wmma::matrix_b,16,16,16,__nv_bfloat16,wmma::row_major> b[4];
        wmma::load_matrix_sync(a[0], smA + (wm*32   )*LDA + k, LDA);
        wmma::load_matrix_sync(a[1], smA + (wm*32+16)*LDA + k, LDA);
        #pragma unroll
        for (int j=0;j<4;j++) wmma::load_matrix_sync(b[j], smB + k*LDB + wn*64 + j*16, LDB);
        #pragma unroll
        for (int i=0;i<2;i++) for (int j=0;j<4;j++) wmma::mma_sync(acc[i][j], a[i], b[j], acc[i][j]);
    }
    __syncthreads();
    #pragma unroll
    for (int i=0;i<2;i++) for (int j=0;j<4;j++)
        wmma::store_matrix_sync(st + (wm*32+i*16)*128 + wn*64 + j*16, acc[i][j], 128, wmma::mem_row_major);
    __syncthreads();

    // xq = (mod + h_b) * q  -> smA (bf16), and restage smB = proj_w
    for (int i = tid; i < 128*128; i += 256){
        int r = i >> 7, c = i & 127;
        float v = (st[i] + h_b[c]) * g_q[(size_t)(row0+r)*128 + c];
        smA[r*LDA + c] = __float2bfloat16(v);
    }
    for (int i = tid; i < 128*16; i += 256){
        int r = i >> 4, c = (i & 15) * 8;
        *(uint4*)(smB + r*LDB + c) = *(const uint4*)(g_wp + (size_t)r*128 + c);
    }
    __syncthreads();

    #pragma unroll
    for (int i=0;i<2;i++) for (int j=0;j<4;j++) wmma::fill_fragment(acc[i][j], 0.0f);
    #pragma unroll
    for (int k=0;k<128;k+=16){
        wmma::fragment<wmma::matrix_a,16,16,16,__nv_bfloat16,wmma::row_major> a[2];
        wmma::fragment<wmma::matrix_b,16,16,16,__nv_bfloat16,wmma::row_major> b[4];
        wmma::load_matrix_sync(a[0], smA + (wm*32   )*LDA + k, LDA);
        wmma::load_matrix_sync(a[1], smA + (wm*32+16)*LDA + k, LDA);
        #pragma unroll
        for (int j=0;j<4;j++) wmma::load_matrix_sync(b[j], smB + k*LDB + wn*64 + j*16, LDB);
        #pragma unroll
        for (int i=0;i<2;i++) for (int j=0;j<4;j++) wmma::mma_sync(acc[i][j], a[i], b[j], acc[i][j]);
    }
    __syncthreads();
    #pragma unroll
    for (int i=0;i<2;i++) for (int j=0;j<4;j++)
        wmma::store_matrix_sync(st + (wm*32+i*16)*128 + wn*64 + j*16, acc[i][j], 128, wmma::mem_row_major);
    __syncthreads();

    for (int i = tid; i < 128*128; i += 256){
        int r = i >> 7, c = i & 127;
        size_t g = (size_t)(row0+r)*128 + c;
        g_x1[g] = st[i] + proj_b[c] + xin[g];
    }
}

// ===== fused MLP: LN2 -> gelu(m@W1+b1) -> @W2 + b2 + x1 -> out =============
__global__ void __launch_bounds__(256,1) g3_kernel(const float* __restrict__ ln2_g,
                                                   const float* __restrict__ ln2_b,
                                                   const float* __restrict__ fc1_b,
                                                   const float* __restrict__ fc2_b,
                                                   float* __restrict__ fout)
{
    extern __shared__ char dsm[];
    __nv_bfloat16* smA  = (__nv_bfloat16*)dsm;             // 128*136*2 = 34816
    __nv_bfloat16* smW1 = (__nv_bfloat16*)(dsm + 34816);   // 128*72*2  = 18432
    __nv_bfloat16* smH  = (__nv_bfloat16*)(dsm + 53248);   // 128*72*2  = 18432
    __nv_bfloat16* smW2 = (__nv_bfloat16*)(dsm + 71680);   // 64*136*2  = 17408
    float*         st   = (float*)(dsm + 89088);           // 128*64*4  = 32768
    const int LD72 = 72, LD136 = 136;
    const int tid  = threadIdx.x;
    const int warp = tid >> 5, lane = tid & 31;
    const int wm   = warp >> 1, wn = warp & 1;
    const int row0 = blockIdx.x * 128;

    // LN2 staging: each warp handles 16 rows
    for (int rr = 0; rr < 16; rr++){
        int r = warp*16 + rr;
        size_t g = (size_t)(row0 + r)*128 + lane*4;
        float4 v = *(const float4*)(g_x1 + g);
        float s  = v.x+v.y+v.z+v.w;
        float s2 = v.x*v.x+v.y*v.y+v.z*v.z+v.w*v.w;
        #pragma unroll
        for (int o=16;o;o>>=1){
            s  += __shfl_xor_sync(0xffffffffu, s,  o);
            s2 += __shfl_xor_sync(0xffffffffu, s2, o);
        }
        float mu  = s * (1.0f/128.0f);
        float var = s2 * (1.0f/128.0f) - mu*mu;
        float rs  = rsqrtf(var + 1e-5f);
        float4 gg = *(const float4*)(ln2_g + lane*4);
        float4 bb = *(const float4*)(ln2_b + lane*4);
        __nv_bfloat162 p0 = __floats2bfloat162_rn((v.x-mu)*rs*gg.x + bb.x, (v.y-mu)*rs*gg.y + bb.y);
        __nv_bfloat162 p1 = __floats2bfloat162_rn((v.z-mu)*rs*gg.z + bb.z, (v.w-mu)*rs*gg.w + bb.w);
        *(__nv_bfloat162*)(smA + r*LDA + lane*4)     = p0;
        *(__nv_bfloat162*)(smA + r*LDA + lane*4 + 2) = p1;
    }

    wmma::fragment<wmma::accumulator,16,16,16,float> acc2[2][4];
    #pragma unroll
    for (int i=0;i<2;i++) for (int j=0;j<4;j++) wmma::fill_fragment(acc2[i][j], 0.0f);

    for (int nc = 0; nc < 8; nc++){
        // stage W1 chunk [128 x 64] (stride 512) and W2 chunk [64 x 128] (stride 128)
        for (int i = tid; i < 128*8; i += 256){
            int r = i >> 3, c = (i & 7) * 8;
            *(uint4*)(smW1 + r*LD72 + c) = *(const uint4*)(g_w1 + (size_t)r*512 + nc*64 + c);
        }
        for (int i = tid; i < 64*16; i += 256){
            int r = i >> 4, c = (i & 15) * 8;
            *(uint4*)(smW2 + r*LD136 + c) = *(const uint4*)(g_w2 + (size_t)(nc*64 + r)*128 + c);
        }
        __syncthreads();

        // h_chunk = m @ W1c  (128x64x128)
        wmma::fragment<wmma::accumulator,16,16,16,float> acc1[2][2];
        #pragma unroll
        for (int i=0;i<2;i++) for (int j=0;j<2;j++) wmma::fill_fragment(acc1[i][j], 0.0f);
        #pragma unroll
        for (int k=0;k<128;k+=16){
            wmma::fragment<wmma::matrix_a,16,16,16,__nv_bfloat16,wmma::row_major> a[2];
            wmma::fragment<wmma::matrix_b,16,16,16,__nv_bfloat16,wmma::row_major> b[2];
            wmma::load_matrix_sync(a[0], smA + (wm*32   )*LDA + k, LDA);
            wmma::load_matrix_sync(a[1], smA + (wm*32+16)*LDA + k, LDA);
            wmma::load_matrix_sync(b[0], smW1 + k*LD72 + wn*32,      LD72);
            wmma::load_matrix_sync(b[1], smW1 + k*LD72 + wn*32 + 16, LD72);
            #pragma unroll
            for (int i=0;i<2;i++) for (int j=0;j<2;j++) wmma::mma_sync(acc1[i][j], a[i], b[j], acc1[i][j]);
        }
        __syncthreads();
        #pragma unroll
        for (int i=0;i<2;i++) for (int j=0;j<2;j++)
            wmma::store_matrix_sync(st + (wm*32+i*16)*64 + wn*32 + j*16, acc1[i][j], 64, wmma::mem_row_major);
        __syncthreads();

        // gelu -> smH (bf16)
        for (int i = tid; i < 128*64; i += 256){
            int r = i >> 6, c = i & 63;
            float v = gelu1(st[i] + fc1_b[nc*64 + c]);
            smH[r*LD72 + c] = __float2bfloat16(v);
        }
        __syncthreads();

        // acc2 += h_chunk @ W2c  (128x128x64)
        #pragma unroll
        for (int k=0;k<64;k+=16){
            wmma::fragment<wmma::matrix_a,16,16,16,__nv_bfloat16,wmma::row_major> a[2];
            wmma::fragment<wmma::matrix_b,16,16,16,__nv_bfloat16,wmma::row_major> b[4];
            wmma::load_matrix_sync(a[0], smH + (wm*32   )*LD72 + k, LD72);
            wmma::load_matrix_sync(a[1], smH + (wm*32+16)*LD72 + k, LD72);
            #pragma unroll
            for (int j=0;j<4;j++) wmma::load_matrix_sync(b[j], smW2 + k*LD136 + wn*64 + j*16, LD136);
            #pragma unroll
            for (int i=0;i<2;i++) for (int j=0;j<4;j++) wmma::mma_sync(acc2[i][j], a[i], b[j], acc2[i][j]);
        }
        __syncthreads();
    }

    // final epilogue: out = acc2 + fc2_b + x1
    float* stO = (float*)dsm;  // 128x128 f32 (64KB) over smA/smW1/smH
    #pragma unroll
    for (int i=0;i<2;i++) for (int j=0;j<4;j++)
        wmma::store_matrix_sync(stO + (wm*32+i*16)*128 + wn*64 + j*16, acc2[i][j], 128, wmma::mem_row_major);
    __syncthreads();
    for (int i = tid; i < 128*128; i += 256){
        int r = i >> 7, c = i & 127;
        size_t g = (size_t)(row0+r)*128 + c;
        fout[g] = stO[i] + fc2_b[c] + g_x1[g];
    }
}

// ---------------- depthwise conv + gelu + gated accumulate ----------------
template<int KS, int LEVEL>
__global__ void __launch_bounds__(256) dwconv_kernel(const float* __restrict__ kern)
{
    __shared__ float sk[KS*KS*CDIM];
    const float* in;
    float* out;
    if      constexpr (LEVEL==0){ in = g_bufA; out = g_bufB; }
    else if constexpr (LEVEL==1){ in = g_bufB; out = g_bufA; }
    else                        { in = g_bufA; out = g_bufB; }

    int tid = threadIdx.y*32 + threadIdx.x;
    for (int i = tid; i < KS*KS*CDIM; i += 256) sk[i] = kern[i];
    __syncthreads();

    int row = blockIdx.x*8 + threadIdx.y;
    int c0  = threadIdx.x * 4;
    int b   = row / LHW;
    int hw  = row - b*LHW;
    int h   = hw / WWD;
    int w   = hw - h*WWD;
    constexpr int P = KS/2;
    float4 acc = make_float4(0.f,0.f,0.f,0.f);
    const float* base = in + (size_t)b*LHW*CDIM + c0;
    #pragma unroll
    for (int kh=0; kh<KS; kh++){
        int hh = h + kh - P;
        if ((unsigned)hh >= HH) continue;
        #pragma unroll
        for (int kw=0; kw<KS; kw++){
            int ww2 = w + kw - P;
            if ((unsigned)ww2 >= WWD) continue;
            float4 vi = *(const float4*)(base + (size_t)(hh*WWD + ww2)*CDIM);
            const float* kp = &sk[(kh*KS+kw)*CDIM + c0];
            acc.x += vi.x*kp[0];
            acc.y += vi.y*kp[1];
            acc.z += vi.z*kp[2];
            acc.w += vi.w*kp[3];
        }
    }
    acc.x = gelu1(acc.x); acc.y = gelu1(acc.y);
    acc.z = gelu1(acc.z); acc.w = gelu1(acc.w);
    *(float4*)(out + (size_t)row*CDIM + c0) = acc;
    float gate = g_gates[row*4 + LEVEL];
    float4* ca = (float4*)(g_ctxall + (size_t)row*CDIM + c0);
    if constexpr (LEVEL==0) {
        *ca = make_float4(acc.x*gate, acc.y*gate, acc.z*gate, acc.w*gate);
    } else {
        float4 o = *ca;
        *ca = make_float4(o.x+acc.x*gate, o.y+acc.y*gate, o.z+acc.z*gate, o.w+acc.w*gate);
    }
}

// ---------------- global-context mean over H,W ----------------
__global__ void mean_zero_kernel(){
    int i = blockIdx.x*256 + threadIdx.x;
    if (i < BATCH*CDIM) g_msum[i] = 0.f;
}
__global__ void mean_partial_kernel(){
    int b = blockIdx.x, chunk = blockIdx.y, c = threadIdx.x;  // 128 threads
    const float* p = g_bufB + ((size_t)b*LHW + chunk*196)*CDIM + c;
    float s = 0.f;
    #pragma unroll 4
    for (int i=0;i<196;i++) s += p[i*CDIM];
    atomicAdd(&g_msum[b*CDIM + c], s);
}
__global__ void mean_final_kernel(){
    int i = blockIdx.x*256 + threadIdx.x;
    if (i < BATCH*CDIM) g_mg[i] = gelu1(g_msum[i] * (1.0f/3136.0f));
}

// ---------------- launch ----------------
extern "C" void kernel_launch(void* const* d_in, const int* in_sizes, int n_in,
                              void* d_out, int out_size)
{
    const float* x      = (const float*)d_in[0];
    const float* f_w    = (const float*)d_in[1];
    const float* f_b    = (const float*)d_in[2];
    const float* k0     = (const float*)d_in[3];
    const float* k1     = (const float*)d_in[4];
    const float* k2     = (const float*)d_in[5];
    const float* h_w    = (const float*)d_in[6];
    const float* h_b    = (const float*)d_in[7];
    const float* proj_w = (const float*)d_in[8];
    const float* proj_b = (const float*)d_in[9];
    const float* ln1_g  = (const float*)d_in[10];
    const float* ln1_b  = (const float*)d_in[11];
    const float* ln2_g  = (const float*)d_in[12];
    const float* ln2_b  = (const float*)d_in[13];
    const float* fc1_w  = (const float*)d_in[14];
    const float* fc1_b  = (const float*)d_in[15];
    const float* fc2_w  = (const float*)d_in[16];
    const float* fc2_b  = (const float*)d_in[17];
    float* out = (float*)d_out;

    // allow >48KB dynamic smem (host-side attr set; not a graphed op)
    cudaFuncSetAttribute(g1_kernel, cudaFuncAttributeMaxDynamicSharedMemorySize, 53248);
    cudaFuncSetAttribute(g2_kernel, cudaFuncAttributeMaxDynamicSharedMemorySize, 135168);
    cudaFuncSetAttribute(g3_kernel, cudaFuncAttributeMaxDynamicSharedMemorySize, 121856);

    // weights -> bf16
    wconv_kernel<<<(128*320+255)/256,256>>>(f_w,    0, 128, 260, 320);
    wconv_kernel<<<(128*128+255)/256,256>>>(h_w,    1, 128, 128, 128);
    wconv_kernel<<<(128*128+255)/256,256>>>(proj_w, 2, 128, 128, 128);
    wconv_kernel<<<(128*512+255)/256,256>>>(fc1_w,  3, 128, 512, 512);
    wconv_kernel<<<(512*128+255)/256,256>>>(fc2_w,  4, 512, 128, 128);

    const int rowBlocks = MROWS/8;
    dim3 cblk(32,8);

    // LN1 -> y (bf16)
    ln_kernel<<<rowBlocks,256>>>(x, ln1_g, ln1_b);

    // t = y@f_w + f_b -> q / ctx(g_bufA) / gates
    dim3 gb1(5, MROWS/128);
    g1_kernel<<<gb1, 256, 53248>>>(f_b);

    // focal levels: conv+gelu+gated accumulate
    dwconv_kernel<3,0><<<rowBlocks,cblk>>>(k0);  // bufA -> bufB
    dwconv_kernel<5,1><<<rowBlocks,cblk>>>(k1);  // bufB -> bufA
    dwconv_kernel<7,2><<<rowBlocks,cblk>>>(k2);  // bufA -> bufB

    // global context: gelu(mean over H,W of last ctx)
    mean_zero_kernel<<<32,256>>>();
    dim3 gmp(64,16);
    mean_partial_kernel<<<gmp,128>>>();
    mean_final_kernel<<<32,256>>>();

    // fused cab -> modulator -> *q -> proj -> +x  => x1
    g2_kernel<<<MROWS/128, 256, 135168>>>(h_b, proj_b, x);

    // fused LN2 -> MLP -> +x1 => out
    g3_kernel<<<MROWS/128, 256, 121856>>>(ln2_g, ln2_b, fc1_b, fc2_b, out);
}